// round 6
// baseline (speedup 1.0000x reference)
#include <cuda_runtime.h>

#define NN      25
#define THREADS 128
#define GPW     32
#define GPB     128
#define INW     21                   // staged row: 18 offset + 3 x (odd stride)
#define OUTW    45                   // staged out row: pos9 | gpos9 | rot27 (odd)
#define WARP_F  ((INW + OUTW) * GPW)            // 2112 floats = 8448 B
#define SMEM_BYTES ((THREADS/32) * WARP_F * 4)  // 33792 B -> 6 blocks/SM

// ---------------- per-node compute: staged smem in, register states, staged smem out ----
template<int I, int N0, int CNT>
__device__ __forceinline__ void proc_node(
    const float* __restrict__ s_in_t,   // lane row base (stride INW across lanes)
    const float4* __restrict__ s_ax,
    float* __restrict__ s_out_t,        // lane row base (stride OUTW)
    float (&stR)[12][9], float (&stP)[12][3],
    float& rx, float& ry, float& rz)
{
    constexpr int J = I - N0;
    const float4 ax = s_ax[I];
    const float th = s_in_t[6*CNT + J] * ax.w;
    const float ox = s_in_t[J*6+0], oy = s_in_t[J*6+1], oz = s_in_t[J*6+2];

    float sx,cx,sy,cy,sz,cz,st,ct;
    __sincosf(s_in_t[J*6+3], &sx, &cx);
    __sincosf(s_in_t[J*6+4], &sy, &cy);
    __sincosf(s_in_t[J*6+5], &sz, &cz);
    __sincosf(th, &st, &ct);

    // E = Rz @ Ry @ Rx
    const float e00=cz*cy,            e10=sz*cy,            e20=-sy;
    const float e01=cz*sy*sx - sz*cx, e11=sz*sy*sx + cz*cx, e21=cy*sx;
    const float e02=cz*sy*cx + sz*sx, e12=sz*sy*cx - cz*sx, e22=cy*cx;

    // Rodrigues with RAW axis
    const float v=1.f-ct, n1=ax.x, n2=ax.y, n3=ax.z;
    const float n12v=n1*n2*v, n13v=n1*n3*v, n23v=n2*n3*v;
    const float r00=ct+n1*n1*v, r01=n12v-n3*st, r02=n13v+n2*st;
    const float r10=n12v+n3*st, r11=ct+n2*n2*v, r12=n23v-n1*st;
    const float r20=n13v-n2*st, r21=n23v+n1*st, r22=ct+n3*n3*v;

    float L[9];
    L[0]=e00*r00+e01*r10+e02*r20; L[1]=e00*r01+e01*r11+e02*r21; L[2]=e00*r02+e01*r12+e02*r22;
    L[3]=e10*r00+e11*r10+e12*r20; L[4]=e10*r01+e11*r11+e12*r21; L[5]=e10*r02+e11*r12+e12*r22;
    L[6]=e20*r00+e21*r10+e22*r20; L[7]=e20*r01+e21*r11+e22*r21; L[8]=e20*r02+e21*r12+e22*r22;

    float R[9], P[3];
    if constexpr (I == 0) {
        #pragma unroll
        for (int k=0;k<9;k++) R[k]=L[k];
        P[0]=0.f; P[1]=0.f; P[2]=0.f;
        rx=ox; ry=oy; rz=oz;                 // gpos = pos + root xyz (induction)
    } else {
        constexpr int Par = (I-1)/2;
        const float d0 = stR[Par][0]*ox + stR[Par][1]*oy + stR[Par][2]*oz;
        const float d1 = stR[Par][3]*ox + stR[Par][4]*oy + stR[Par][5]*oz;
        const float d2 = stR[Par][6]*ox + stR[Par][7]*oy + stR[Par][8]*oz;
        P[0]=d0+stP[Par][0]; P[1]=d1+stP[Par][1]; P[2]=d2+stP[Par][2];
        #pragma unroll
        for (int r=0;r<3;r++)
            #pragma unroll
            for (int c=0;c<3;c++)
                R[r*3+c]=stR[Par][r*3+0]*L[c]+stR[Par][r*3+1]*L[3+c]+stR[Par][r*3+2]*L[6+c];
    }

    // stage outputs: pos | gpos | rot
    s_out_t[J*3+0]=P[0]; s_out_t[J*3+1]=P[1]; s_out_t[J*3+2]=P[2];
    s_out_t[3*CNT+J*3+0]=P[0]+rx; s_out_t[3*CNT+J*3+1]=P[1]+ry; s_out_t[3*CNT+J*3+2]=P[2]+rz;
    #pragma unroll
    for (int k=0;k<9;k++) s_out_t[6*CNT+J*9+k]=R[k];

    if constexpr (I < 12) {           // nodes >= 12 have no children
        #pragma unroll
        for (int k=0;k<9;k++) stR[I][k]=R[k];
        stP[I][0]=P[0]; stP[I][1]=P[1]; stP[I][2]=P[2];
    }
}

// flat coalesced flush: CF floats per graph, contiguous in global per graph
template<int CF, int OSTRIDE>
__device__ __forceinline__ void flush_flat(
    float* __restrict__ dst, const float* __restrict__ src, int src_off, int lane)
{
    #pragma unroll
    for (int it = 0; it < CF; it++) {
        const int idx = lane + 32 * it;            // CF*32 total elements
        const int g = idx / CF;
        const int j = idx - g * CF;
        dst[g * OSTRIDE + j] = src[g * OUTW + src_off + j];
    }
}

// ---------------- one CNT-node chunk: stage inputs -> compute -> coalesced flush --------
template<int N0, int CNT>
__device__ __forceinline__ void run_chunk(
    const float* __restrict__ x, const float* __restrict__ off, size_t gw0, int lane,
    float* __restrict__ s_in, const float* __restrict__ s_in_t,
    const float4* __restrict__ s_ax,
    float* __restrict__ s_out, float* __restrict__ s_out_t,
    float* __restrict__ out_pos, float* __restrict__ out_rot, float* __restrict__ out_gpos,
    float (&stR)[12][9], float (&stP)[12][3], float& rx, float& ry, float& rz)
{
    // stage offsets: flat over 32 graphs x 6*CNT floats (high LDG MLP)
    {
        constexpr int CF = 6 * CNT;
        const float* srcO = off + gw0*150 + N0*6;
        #pragma unroll
        for (int it = 0; it < CF; it++) {
            const int idx = lane + 32 * it;
            const int g = idx / CF;
            const int j = idx - g * CF;
            s_in[g*INW + j] = srcO[(size_t)g*150 + j];
        }
    }
    // stage x: flat over 32 graphs x CNT floats
    {
        const float* xb = x + gw0*25 + N0;
        #pragma unroll
        for (int it = 0; it < CNT; it++) {
            const int idx = lane + 32 * it;
            const int g = idx / CNT;
            const int j = idx - g * CNT;
            s_in[g*INW + 6*CNT + j] = xb[(size_t)g*25 + j];
        }
    }
    __syncwarp();

    proc_node<N0+0,N0,CNT>(s_in_t, s_ax, s_out_t, stR, stP, rx,ry,rz);
    if constexpr (CNT > 1) proc_node<N0+1,N0,CNT>(s_in_t, s_ax, s_out_t, stR, stP, rx,ry,rz);
    if constexpr (CNT > 2) proc_node<N0+2,N0,CNT>(s_in_t, s_ax, s_out_t, stR, stP, rx,ry,rz);
    __syncwarp();

    flush_flat<3*CNT,  75>(out_pos  + gw0*75  + N0*3, s_out, 0,     lane);
    flush_flat<3*CNT,  75>(out_gpos + gw0*75  + N0*3, s_out, 3*CNT, lane);
    flush_flat<9*CNT, 225>(out_rot  + gw0*225 + N0*9, s_out, 6*CNT, lane);
    __syncwarp();   // WAR protection before s_in/s_out reuse
}

__global__ void __launch_bounds__(THREADS, 6)
fk_kernel(const float* __restrict__ x,
          const float* __restrict__ off,
          const float* __restrict__ axis,
          float* __restrict__ out_pos,
          float* __restrict__ out_rot,
          float* __restrict__ out_gpos)
{
    extern __shared__ float sm[];
    __shared__ float4 s_ax[NN];

    const int t = threadIdx.x;
    if (t < NN) {
        const float a0 = axis[t*3+0], a1 = axis[t*3+1], a2 = axis[t*3+2];
        s_ax[t] = make_float4(a0, a1, a2, sqrtf(a0*a0 + a1*a1 + a2*a2));
    }
    __syncthreads();

    const int lane = t & 31, w = t >> 5;
    float* s_warp = sm + w * WARP_F;
    float* s_in   = s_warp;                 // [32][21]
    float* s_out  = s_warp + GPW * INW;     // [32][45]

    const size_t gw0 = (size_t)blockIdx.x * GPB + (size_t)w * GPW;

    const float* s_in_t  = s_in  + lane * INW;
    float*       s_out_t = s_out + lane * OUTW;

    float stR[12][9], stP[12][3];
    float rx = 0.f, ry = 0.f, rz = 0.f;

    run_chunk<0 ,3>(x, off, gw0, lane, s_in, s_in_t, s_ax, s_out, s_out_t,
                    out_pos, out_rot, out_gpos, stR, stP, rx, ry, rz);
    run_chunk<3 ,3>(x, off, gw0, lane, s_in, s_in_t, s_ax, s_out, s_out_t,
                    out_pos, out_rot, out_gpos, stR, stP, rx, ry, rz);
    run_chunk<6 ,3>(x, off, gw0, lane, s_in, s_in_t, s_ax, s_out, s_out_t,
                    out_pos, out_rot, out_gpos, stR, stP, rx, ry, rz);
    run_chunk<9 ,3>(x, off, gw0, lane, s_in, s_in_t, s_ax, s_out, s_out_t,
                    out_pos, out_rot, out_gpos, stR, stP, rx, ry, rz);
    run_chunk<12,3>(x, off, gw0, lane, s_in, s_in_t, s_ax, s_out, s_out_t,
                    out_pos, out_rot, out_gpos, stR, stP, rx, ry, rz);
    run_chunk<15,3>(x, off, gw0, lane, s_in, s_in_t, s_ax, s_out, s_out_t,
                    out_pos, out_rot, out_gpos, stR, stP, rx, ry, rz);
    run_chunk<18,3>(x, off, gw0, lane, s_in, s_in_t, s_ax, s_out, s_out_t,
                    out_pos, out_rot, out_gpos, stR, stP, rx, ry, rz);
    run_chunk<21,3>(x, off, gw0, lane, s_in, s_in_t, s_ax, s_out, s_out_t,
                    out_pos, out_rot, out_gpos, stR, stP, rx, ry, rz);
    run_chunk<24,1>(x, off, gw0, lane, s_in, s_in_t, s_ax, s_out, s_out_t,
                    out_pos, out_rot, out_gpos, stR, stP, rx, ry, rz);
}

// ---------- naive tail kernel for G % 128 != 0 (not used for the bench shape) ----------
__global__ void fk_tail_kernel(const float* __restrict__ x,
                               const float* __restrict__ off,
                               const float* __restrict__ axis,
                               float* __restrict__ out_pos,
                               float* __restrict__ out_rot,
                               float* __restrict__ out_gpos,
                               int g0, int G)
{
    const int g = g0 + blockIdx.x * blockDim.x + threadIdx.x;
    if (g >= G) return;
    float R[NN][9], Ps[NN][3], Gs[NN][3];
    for (int i = 0; i < NN; i++) {
        const int idx = g * NN + i;
        const float a0 = axis[i*3+0], a1 = axis[i*3+1], a2 = axis[i*3+2];
        const float th = x[idx] * sqrtf(a0*a0+a1*a1+a2*a2);
        const float* o = off + (size_t)idx * 6;
        const float ox=o[0], oy=o[1], oz=o[2];
        float sx,cx,sy,cy,sz,cz,st,ct;
        __sincosf(o[3],&sx,&cx); __sincosf(o[4],&sy,&cy); __sincosf(o[5],&sz,&cz);
        __sincosf(th,&st,&ct);
        const float e00=cz*cy, e10=sz*cy, e20=-sy;
        const float e01=cz*sy*sx-sz*cx, e11=sz*sy*sx+cz*cx, e21=cy*sx;
        const float e02=cz*sy*cx+sz*sx, e12=sz*sy*cx-cz*sx, e22=cy*cx;
        const float v=1.f-ct;
        const float r00=ct+a0*a0*v, r01=a0*a1*v-a2*st, r02=a0*a2*v+a1*st;
        const float r10=a0*a1*v+a2*st, r11=ct+a1*a1*v, r12=a1*a2*v-a0*st;
        const float r20=a0*a2*v-a1*st, r21=a1*a2*v+a0*st, r22=ct+a2*a2*v;
        float L[9];
        L[0]=e00*r00+e01*r10+e02*r20; L[1]=e00*r01+e01*r11+e02*r21; L[2]=e00*r02+e01*r12+e02*r22;
        L[3]=e10*r00+e11*r10+e12*r20; L[4]=e10*r01+e11*r11+e12*r21; L[5]=e10*r02+e11*r12+e12*r22;
        L[6]=e20*r00+e21*r10+e22*r20; L[7]=e20*r01+e21*r11+e22*r21; L[8]=e20*r02+e21*r12+e22*r22;
        if (i == 0) {
            Ps[0][0]=Ps[0][1]=Ps[0][2]=0.f;
            Gs[0][0]=ox; Gs[0][1]=oy; Gs[0][2]=oz;
            for (int k=0;k<9;k++) R[0][k]=L[k];
        } else {
            const int p=(i-1)/2;
            const float d0=R[p][0]*ox+R[p][1]*oy+R[p][2]*oz;
            const float d1=R[p][3]*ox+R[p][4]*oy+R[p][5]*oz;
            const float d2=R[p][6]*ox+R[p][7]*oy+R[p][8]*oz;
            Ps[i][0]=d0+Ps[p][0]; Ps[i][1]=d1+Ps[p][1]; Ps[i][2]=d2+Ps[p][2];
            Gs[i][0]=d0+Gs[p][0]; Gs[i][1]=d1+Gs[p][1]; Gs[i][2]=d2+Gs[p][2];
            for (int r=0;r<3;r++) for (int c=0;c<3;c++)
                R[i][r*3+c]=R[p][r*3+0]*L[c]+R[p][r*3+1]*L[3+c]+R[p][r*3+2]*L[6+c];
        }
        const int p3=idx*3, p9=idx*9;
        out_pos[p3+0]=Ps[i][0]; out_pos[p3+1]=Ps[i][1]; out_pos[p3+2]=Ps[i][2];
        out_gpos[p3+0]=Gs[i][0]; out_gpos[p3+1]=Gs[i][1]; out_gpos[p3+2]=Gs[i][2];
        for (int k=0;k<9;k++) out_rot[p9+k]=R[i][k];
    }
}

extern "C" void kernel_launch(void* const* d_in, const int* in_sizes, int n_in,
                              void* d_out, int out_size)
{
    const float* x = (const float*)d_in[0];
    const int gn = in_sizes[0];          // G * 25
    const int G  = gn / NN;

    const float* off = nullptr;
    const float* axis = nullptr;
    for (int i = 1; i < n_in; i++) {
        if (in_sizes[i] == 6 * gn) off = (const float*)d_in[i];
        else if (in_sizes[i] == 3 * gn && axis == nullptr) axis = (const float*)d_in[i];
    }

    float* out = (float*)d_out;
    float* out_pos  = out;                    // G*N*3
    float* out_rot  = out + (size_t)gn * 3;   // G*N*9
    float* out_gpos = out + (size_t)gn * 12;  // G*N*3
    (void)out_size;

    static bool attr_set = false;
    if (!attr_set) {
        cudaFuncSetAttribute(fk_kernel, cudaFuncAttributeMaxDynamicSharedMemorySize, SMEM_BYTES);
        attr_set = true;
    }

    const int full_blocks = G / GPB;
    if (full_blocks > 0)
        fk_kernel<<<full_blocks, THREADS, SMEM_BYTES>>>(x, off, axis, out_pos, out_rot, out_gpos);
    const int rem = G - full_blocks * GPB;
    if (rem > 0) {
        const int tb = 128;
        fk_tail_kernel<<<(rem + tb - 1) / tb, tb>>>(x, off, axis, out_pos, out_rot, out_gpos,
                                                    full_blocks * GPB, G);
    }
}

// round 7
// speedup vs baseline: 1.1757x; 1.1757x over previous
#include <cuda_runtime.h>

#define NN      25
#define THREADS 128
#define GPW     32
#define GPB     128
#define INW     21                   // staged row: up to 18 offset + 3 x (odd stride)
#define OUTW    45                   // staged out row: up to pos9 | gpos9 | rot27 (odd)
#define WARP_F  ((INW + OUTW) * GPW)            // 2112 floats = 8448 B
#define SMEM_BYTES ((THREADS/32) * WARP_F * 4)  // 33792 B

// ---------------- per-node compute: staged smem in, register states, staged smem out ----
template<int I, int N0, int CNT>
__device__ __forceinline__ void proc_node(
    const float* __restrict__ s_in_t,   // lane row base (stride INW across lanes)
    const float4* __restrict__ s_ax,
    float* __restrict__ s_out_t,        // lane row base (stride OUTW)
    float (&stR)[12][9], float (&stP)[12][3],
    float& rx, float& ry, float& rz)
{
    constexpr int J = I - N0;
    const float4 ax = s_ax[I];
    const float th = s_in_t[6*CNT + J] * ax.w;
    const float ox = s_in_t[J*6+0], oy = s_in_t[J*6+1], oz = s_in_t[J*6+2];

    float sx,cx,sy,cy,sz,cz,st,ct;
    __sincosf(s_in_t[J*6+3], &sx, &cx);
    __sincosf(s_in_t[J*6+4], &sy, &cy);
    __sincosf(s_in_t[J*6+5], &sz, &cz);
    __sincosf(th, &st, &ct);

    // E = Rz @ Ry @ Rx
    const float e00=cz*cy,            e10=sz*cy,            e20=-sy;
    const float e01=cz*sy*sx - sz*cx, e11=sz*sy*sx + cz*cx, e21=cy*sx;
    const float e02=cz*sy*cx + sz*sx, e12=sz*sy*cx - cz*sx, e22=cy*cx;

    // Rodrigues with RAW axis
    const float v=1.f-ct, n1=ax.x, n2=ax.y, n3=ax.z;
    const float n12v=n1*n2*v, n13v=n1*n3*v, n23v=n2*n3*v;
    const float r00=ct+n1*n1*v, r01=n12v-n3*st, r02=n13v+n2*st;
    const float r10=n12v+n3*st, r11=ct+n2*n2*v, r12=n23v-n1*st;
    const float r20=n13v-n2*st, r21=n23v+n1*st, r22=ct+n3*n3*v;

    float L[9];
    L[0]=e00*r00+e01*r10+e02*r20; L[1]=e00*r01+e01*r11+e02*r21; L[2]=e00*r02+e01*r12+e02*r22;
    L[3]=e10*r00+e11*r10+e12*r20; L[4]=e10*r01+e11*r11+e12*r21; L[5]=e10*r02+e11*r12+e12*r22;
    L[6]=e20*r00+e21*r10+e22*r20; L[7]=e20*r01+e21*r11+e22*r21; L[8]=e20*r02+e21*r12+e22*r22;

    float R[9], P[3];
    if constexpr (I == 0) {
        #pragma unroll
        for (int k=0;k<9;k++) R[k]=L[k];
        P[0]=0.f; P[1]=0.f; P[2]=0.f;
        rx=ox; ry=oy; rz=oz;                 // gpos = pos + root xyz (induction)
    } else {
        constexpr int Par = (I-1)/2;
        const float d0 = stR[Par][0]*ox + stR[Par][1]*oy + stR[Par][2]*oz;
        const float d1 = stR[Par][3]*ox + stR[Par][4]*oy + stR[Par][5]*oz;
        const float d2 = stR[Par][6]*ox + stR[Par][7]*oy + stR[Par][8]*oz;
        P[0]=d0+stP[Par][0]; P[1]=d1+stP[Par][1]; P[2]=d2+stP[Par][2];
        #pragma unroll
        for (int r=0;r<3;r++)
            #pragma unroll
            for (int c=0;c<3;c++)
                R[r*3+c]=stR[Par][r*3+0]*L[c]+stR[Par][r*3+1]*L[3+c]+stR[Par][r*3+2]*L[6+c];
    }

    // stage outputs: pos | gpos | rot
    s_out_t[J*3+0]=P[0]; s_out_t[J*3+1]=P[1]; s_out_t[J*3+2]=P[2];
    s_out_t[3*CNT+J*3+0]=P[0]+rx; s_out_t[3*CNT+J*3+1]=P[1]+ry; s_out_t[3*CNT+J*3+2]=P[2]+rz;
    #pragma unroll
    for (int k=0;k<9;k++) s_out_t[6*CNT+J*9+k]=R[k];

    if constexpr (I < 12) {           // node 12+ are never parents of valid nodes
        #pragma unroll
        for (int k=0;k<9;k++) stR[I][k]=R[k];
        stP[I][0]=P[0]; stP[I][1]=P[1]; stP[I][2]=P[2];
    }
}

// flat coalesced flush: CF floats per graph, contiguous in global per graph
template<int CF, int OSTRIDE>
__device__ __forceinline__ void flush_flat(
    float* __restrict__ dst, const float* __restrict__ src, int src_off, int lane)
{
    #pragma unroll
    for (int it = 0; it < CF; it++) {
        const int idx = lane + 32 * it;            // CF*32 total elements
        const int g = idx / CF;
        const int j = idx - g * CF;
        dst[g * OSTRIDE + j] = src[g * OUTW + src_off + j];
    }
}

// ---------------- one CNT-node chunk: stage inputs -> compute -> coalesced flush --------
template<int N0, int CNT>
__device__ __forceinline__ void run_chunk(
    const float* __restrict__ x, const float* __restrict__ off, size_t gw0, int lane,
    float* __restrict__ s_in, const float* __restrict__ s_in_t,
    const float4* __restrict__ s_ax,
    float* __restrict__ s_out, float* __restrict__ s_out_t,
    float* __restrict__ out_pos, float* __restrict__ out_rot, float* __restrict__ out_gpos,
    float (&stR)[12][9], float (&stP)[12][3], float& rx, float& ry, float& rz)
{
    // stage offsets: flat over 32 graphs x 6*CNT floats (high LDG MLP)
    {
        constexpr int CF = 6 * CNT;
        const float* srcO = off + gw0*150 + N0*6;
        #pragma unroll
        for (int it = 0; it < CF; it++) {
            const int idx = lane + 32 * it;
            const int g = idx / CF;
            const int j = idx - g * CF;
            s_in[g*INW + j] = srcO[(size_t)g*150 + j];
        }
    }
    // stage x: flat over 32 graphs x CNT floats
    {
        const float* xb = x + gw0*25 + N0;
        #pragma unroll
        for (int it = 0; it < CNT; it++) {
            const int idx = lane + 32 * it;
            const int g = idx / CNT;
            const int j = idx - g * CNT;
            s_in[g*INW + 6*CNT + j] = xb[(size_t)g*25 + j];
        }
    }
    __syncwarp();

    proc_node<N0+0,N0,CNT>(s_in_t, s_ax, s_out_t, stR, stP, rx,ry,rz);
    if constexpr (CNT > 1) proc_node<N0+1,N0,CNT>(s_in_t, s_ax, s_out_t, stR, stP, rx,ry,rz);
    if constexpr (CNT > 2) proc_node<N0+2,N0,CNT>(s_in_t, s_ax, s_out_t, stR, stP, rx,ry,rz);
    __syncwarp();

    flush_flat<3*CNT,  75>(out_pos  + gw0*75  + N0*3, s_out, 0,     lane);
    flush_flat<3*CNT,  75>(out_gpos + gw0*75  + N0*3, s_out, 3*CNT, lane);
    flush_flat<9*CNT, 225>(out_rot  + gw0*225 + N0*9, s_out, 6*CNT, lane);
    __syncwarp();   // WAR protection before s_in/s_out reuse
}

__global__ void __launch_bounds__(THREADS, 5)
fk_kernel(const float* __restrict__ x,
          const float* __restrict__ off,
          const float* __restrict__ axis,
          float* __restrict__ out_pos,
          float* __restrict__ out_rot,
          float* __restrict__ out_gpos)
{
    extern __shared__ float sm[];
    __shared__ float4 s_ax[NN];

    const int t = threadIdx.x;
    if (t < NN) {
        const float a0 = axis[t*3+0], a1 = axis[t*3+1], a2 = axis[t*3+2];
        s_ax[t] = make_float4(a0, a1, a2, sqrtf(a0*a0 + a1*a1 + a2*a2));
    }
    __syncthreads();

    const int lane = t & 31, w = t >> 5;
    float* s_warp = sm + w * WARP_F;
    float* s_in   = s_warp;                 // [32][21]
    float* s_out  = s_warp + GPW * INW;     // [32][45]

    const size_t gw0 = (size_t)blockIdx.x * GPB + (size_t)w * GPW;

    const float* s_in_t  = s_in  + lane * INW;
    float*       s_out_t = s_out + lane * OUTW;

    float stR[12][9], stP[12][3];
    float rx = 0.f, ry = 0.f, rz = 0.f;

    // Subtree-ordered schedule: max 4 parent states live at any point ({2,4,7,8}),
    // every chunk is a contiguous node range, parents always precede children.
    run_chunk<0 ,3>(x, off, gw0, lane, s_in, s_in_t, s_ax, s_out, s_out_t,
                    out_pos, out_rot, out_gpos, stR, stP, rx, ry, rz);   // 0,1,2
    run_chunk<3 ,2>(x, off, gw0, lane, s_in, s_in_t, s_ax, s_out, s_out_t,
                    out_pos, out_rot, out_gpos, stR, stP, rx, ry, rz);   // 3,4   (par 1)
    run_chunk<7 ,2>(x, off, gw0, lane, s_in, s_in_t, s_ax, s_out, s_out_t,
                    out_pos, out_rot, out_gpos, stR, stP, rx, ry, rz);   // 7,8   (par 3)
    run_chunk<15,2>(x, off, gw0, lane, s_in, s_in_t, s_ax, s_out, s_out_t,
                    out_pos, out_rot, out_gpos, stR, stP, rx, ry, rz);   // 15,16 (par 7)
    run_chunk<17,2>(x, off, gw0, lane, s_in, s_in_t, s_ax, s_out, s_out_t,
                    out_pos, out_rot, out_gpos, stR, stP, rx, ry, rz);   // 17,18 (par 8)
    run_chunk<9 ,2>(x, off, gw0, lane, s_in, s_in_t, s_ax, s_out, s_out_t,
                    out_pos, out_rot, out_gpos, stR, stP, rx, ry, rz);   // 9,10  (par 4)
    run_chunk<19,2>(x, off, gw0, lane, s_in, s_in_t, s_ax, s_out, s_out_t,
                    out_pos, out_rot, out_gpos, stR, stP, rx, ry, rz);   // 19,20 (par 9)
    run_chunk<21,2>(x, off, gw0, lane, s_in, s_in_t, s_ax, s_out, s_out_t,
                    out_pos, out_rot, out_gpos, stR, stP, rx, ry, rz);   // 21,22 (par 10)
    run_chunk<5 ,2>(x, off, gw0, lane, s_in, s_in_t, s_ax, s_out, s_out_t,
                    out_pos, out_rot, out_gpos, stR, stP, rx, ry, rz);   // 5,6   (par 2)
    run_chunk<11,2>(x, off, gw0, lane, s_in, s_in_t, s_ax, s_out, s_out_t,
                    out_pos, out_rot, out_gpos, stR, stP, rx, ry, rz);   // 11,12 (par 5)
    run_chunk<13,2>(x, off, gw0, lane, s_in, s_in_t, s_ax, s_out, s_out_t,
                    out_pos, out_rot, out_gpos, stR, stP, rx, ry, rz);   // 13,14 (par 6)
    run_chunk<23,2>(x, off, gw0, lane, s_in, s_in_t, s_ax, s_out, s_out_t,
                    out_pos, out_rot, out_gpos, stR, stP, rx, ry, rz);   // 23,24 (par 11)
}

// ---------- naive tail kernel for G % 128 != 0 (not used for the bench shape) ----------
__global__ void fk_tail_kernel(const float* __restrict__ x,
                               const float* __restrict__ off,
                               const float* __restrict__ axis,
                               float* __restrict__ out_pos,
                               float* __restrict__ out_rot,
                               float* __restrict__ out_gpos,
                               int g0, int G)
{
    const int g = g0 + blockIdx.x * blockDim.x + threadIdx.x;
    if (g >= G) return;
    float R[NN][9], Ps[NN][3], Gs[NN][3];
    for (int i = 0; i < NN; i++) {
        const int idx = g * NN + i;
        const float a0 = axis[i*3+0], a1 = axis[i*3+1], a2 = axis[i*3+2];
        const float th = x[idx] * sqrtf(a0*a0+a1*a1+a2*a2);
        const float* o = off + (size_t)idx * 6;
        const float ox=o[0], oy=o[1], oz=o[2];
        float sx,cx,sy,cy,sz,cz,st,ct;
        __sincosf(o[3],&sx,&cx); __sincosf(o[4],&sy,&cy); __sincosf(o[5],&sz,&cz);
        __sincosf(th,&st,&ct);
        const float e00=cz*cy, e10=sz*cy, e20=-sy;
        const float e01=cz*sy*sx-sz*cx, e11=sz*sy*sx+cz*cx, e21=cy*sx;
        const float e02=cz*sy*cx+sz*sx, e12=sz*sy*cx-cz*sx, e22=cy*cx;
        const float v=1.f-ct;
        const float r00=ct+a0*a0*v, r01=a0*a1*v-a2*st, r02=a0*a2*v+a1*st;
        const float r10=a0*a1*v+a2*st, r11=ct+a1*a1*v, r12=a1*a2*v-a0*st;
        const float r20=a0*a2*v-a1*st, r21=a1*a2*v+a0*st, r22=ct+a2*a2*v;
        float L[9];
        L[0]=e00*r00+e01*r10+e02*r20; L[1]=e00*r01+e01*r11+e02*r21; L[2]=e00*r02+e01*r12+e02*r22;
        L[3]=e10*r00+e11*r10+e12*r20; L[4]=e10*r01+e11*r11+e12*r21; L[5]=e10*r02+e11*r12+e12*r22;
        L[6]=e20*r00+e21*r10+e22*r20; L[7]=e20*r01+e21*r11+e22*r21; L[8]=e20*r02+e21*r12+e22*r22;
        if (i == 0) {
            Ps[0][0]=Ps[0][1]=Ps[0][2]=0.f;
            Gs[0][0]=ox; Gs[0][1]=oy; Gs[0][2]=oz;
            for (int k=0;k<9;k++) R[0][k]=L[k];
        } else {
            const int p=(i-1)/2;
            const float d0=R[p][0]*ox+R[p][1]*oy+R[p][2]*oz;
            const float d1=R[p][3]*ox+R[p][4]*oy+R[p][5]*oz;
            const float d2=R[p][6]*ox+R[p][7]*oy+R[p][8]*oz;
            Ps[i][0]=d0+Ps[p][0]; Ps[i][1]=d1+Ps[p][1]; Ps[i][2]=d2+Ps[p][2];
            Gs[i][0]=d0+Gs[p][0]; Gs[i][1]=d1+Gs[p][1]; Gs[i][2]=d2+Gs[p][2];
            for (int r=0;r<3;r++) for (int c=0;c<3;c++)
                R[i][r*3+c]=R[p][r*3+0]*L[c]+R[p][r*3+1]*L[3+c]+R[p][r*3+2]*L[6+c];
        }
        const int p3=idx*3, p9=idx*9;
        out_pos[p3+0]=Ps[i][0]; out_pos[p3+1]=Ps[i][1]; out_pos[p3+2]=Ps[i][2];
        out_gpos[p3+0]=Gs[i][0]; out_gpos[p3+1]=Gs[i][1]; out_gpos[p3+2]=Gs[i][2];
        for (int k=0;k<9;k++) out_rot[p9+k]=R[i][k];
    }
}

extern "C" void kernel_launch(void* const* d_in, const int* in_sizes, int n_in,
                              void* d_out, int out_size)
{
    const float* x = (const float*)d_in[0];
    const int gn = in_sizes[0];          // G * 25
    const int G  = gn / NN;

    const float* off = nullptr;
    const float* axis = nullptr;
    for (int i = 1; i < n_in; i++) {
        if (in_sizes[i] == 6 * gn) off = (const float*)d_in[i];
        else if (in_sizes[i] == 3 * gn && axis == nullptr) axis = (const float*)d_in[i];
    }

    float* out = (float*)d_out;
    float* out_pos  = out;                    // G*N*3
    float* out_rot  = out + (size_t)gn * 3;   // G*N*9
    float* out_gpos = out + (size_t)gn * 12;  // G*N*3
    (void)out_size;

    static bool attr_set = false;
    if (!attr_set) {
        cudaFuncSetAttribute(fk_kernel, cudaFuncAttributeMaxDynamicSharedMemorySize, SMEM_BYTES);
        attr_set = true;
    }

    const int full_blocks = G / GPB;
    if (full_blocks > 0)
        fk_kernel<<<full_blocks, THREADS, SMEM_BYTES>>>(x, off, axis, out_pos, out_rot, out_gpos);
    const int rem = G - full_blocks * GPB;
    if (rem > 0) {
        const int tb = 128;
        fk_tail_kernel<<<(rem + tb - 1) / tb, tb>>>(x, off, axis, out_pos, out_rot, out_gpos,
                                                    full_blocks * GPB, G);
    }
}

// round 8
// speedup vs baseline: 3.3451x; 2.8452x over previous
#include <cuda_runtime.h>

#define NN    25
#define GPBK  8               // graphs per block
#define THREADS 224           // 200 active compute threads (8*25), 24 help stage/flush
#define OFFW  7               // s_off row stride (6 used, odd -> conflict-free)
#define LW    9               // s_L row stride (9 used, odd)
#define OUTW  15              // s_out row stride (15 used, odd)

// Root-to-node path (after the root), -1 padded. parent(i) = (i-1)/2.
__constant__ int c_path[NN][4] = {
    {-1,-1,-1,-1},
    { 1,-1,-1,-1},{ 2,-1,-1,-1},
    { 1, 3,-1,-1},{ 1, 4,-1,-1},{ 2, 5,-1,-1},{ 2, 6,-1,-1},
    { 1, 3, 7,-1},{ 1, 3, 8,-1},{ 1, 4, 9,-1},{ 1, 4,10,-1},
    { 2, 5,11,-1},{ 2, 5,12,-1},{ 2, 6,13,-1},{ 2, 6,14,-1},
    { 1, 3, 7,15},{ 1, 3, 7,16},{ 1, 3, 8,17},{ 1, 3, 8,18},
    { 1, 4, 9,19},{ 1, 4, 9,20},{ 1, 4,10,21},{ 1, 4,10,22},
    { 2, 5,11,23},{ 2, 5,11,24}
};

__global__ void __launch_bounds__(THREADS, 6)
fk_kernel(const float* __restrict__ x,
          const float* __restrict__ off,
          const float* __restrict__ axis,
          float* __restrict__ out_pos,
          float* __restrict__ out_rot,
          float* __restrict__ out_gpos,
          int G)
{
    __shared__ float  s_off[GPBK * NN * OFFW];   // 1400 floats
    __shared__ float  s_L  [GPBK * NN * LW];     // 1800 floats
    __shared__ float  s_out[GPBK * NN * OUTW];   // 3000 floats
    __shared__ float4 s_ax[NN];

    const int t  = threadIdx.x;
    const int g0 = blockIdx.x * GPBK;
    const int ng = min(GPBK, G - g0);
    const int NT = ng * NN;

    if (t < NN) {
        const float a0 = axis[t*3+0], a1 = axis[t*3+1], a2 = axis[t*3+2];
        s_ax[t] = make_float4(a0, a1, a2, sqrtf(a0*a0 + a1*a1 + a2*a2));
    }
    // stage offsets: ng*150 contiguous floats, coalesced
    for (int idx = t; idx < NT * 6; idx += THREADS) {
        const int row = idx / 6;
        const int j   = idx - row * 6;
        s_off[row * OFFW + j] = off[(size_t)g0 * 150 + idx];
    }
    __syncthreads();

    // ---- phase 1: each thread builds its node's local matrix L -> smem ----
    if (t < NT) {
        const int i = t % NN;
        const float* o = s_off + t * OFFW;
        const float4 ax = s_ax[i];
        const float th = x[(size_t)g0 * NN + t] * ax.w;   // coalesced LDG

        float sx,cx,sy,cy,sz,cz,st,ct;
        __sincosf(o[3], &sx, &cx);
        __sincosf(o[4], &sy, &cy);
        __sincosf(o[5], &sz, &cz);
        __sincosf(th,  &st, &ct);

        // E = Rz @ Ry @ Rx
        const float e00=cz*cy,            e10=sz*cy,            e20=-sy;
        const float e01=cz*sy*sx - sz*cx, e11=sz*sy*sx + cz*cx, e21=cy*sx;
        const float e02=cz*sy*cx + sz*sx, e12=sz*sy*cx - cz*sx, e22=cy*cx;

        // Rodrigues with RAW axis
        const float v=1.f-ct, n1=ax.x, n2=ax.y, n3=ax.z;
        const float n12v=n1*n2*v, n13v=n1*n3*v, n23v=n2*n3*v;
        const float r00=ct+n1*n1*v, r01=n12v-n3*st, r02=n13v+n2*st;
        const float r10=n12v+n3*st, r11=ct+n2*n2*v, r12=n23v-n1*st;
        const float r20=n13v-n2*st, r21=n23v+n1*st, r22=ct+n3*n3*v;

        float* Ld = s_L + t * LW;
        Ld[0]=e00*r00+e01*r10+e02*r20; Ld[1]=e00*r01+e01*r11+e02*r21; Ld[2]=e00*r02+e01*r12+e02*r22;
        Ld[3]=e10*r00+e11*r10+e12*r20; Ld[4]=e10*r01+e11*r11+e12*r21; Ld[5]=e10*r02+e11*r12+e12*r22;
        Ld[6]=e20*r00+e21*r10+e22*r20; Ld[7]=e20*r01+e21*r11+e22*r21; Ld[8]=e20*r02+e21*r12+e22*r22;
    }
    __syncthreads();

    // ---- phase 2: each thread walks its root path (prefix product), no shared state ----
    if (t < NT) {
        const int gl = t / NN;
        const int i  = t - gl * NN;
        const float* Lb = s_L   + gl * NN * LW;
        const float* ob = s_off + gl * NN * OFFW;

        float R[9];
        #pragma unroll
        for (int k = 0; k < 9; k++) R[k] = Lb[k];      // root local (row 0)
        float p0 = 0.f, p1 = 0.f, p2 = 0.f;

        #pragma unroll
        for (int k = 0; k < 4; k++) {
            const int a  = c_path[i][k];
            const bool vld = (a >= 0);
            const int aa = vld ? a : 0;                 // safe clamp
            const float* oa = ob + aa * OFFW;
            const float ox = oa[0], oy = oa[1], oz = oa[2];
            const float d0 = R[0]*ox + R[1]*oy + R[2]*oz;
            const float d1 = R[3]*ox + R[4]*oy + R[5]*oz;
            const float d2 = R[6]*ox + R[7]*oy + R[8]*oz;
            const float* La = Lb + aa * LW;
            float Nw[9];
            #pragma unroll
            for (int r = 0; r < 3; r++)
                #pragma unroll
                for (int c = 0; c < 3; c++)
                    Nw[r*3+c] = R[r*3+0]*La[c] + R[r*3+1]*La[3+c] + R[r*3+2]*La[6+c];
            p0 = vld ? p0 + d0 : p0;
            p1 = vld ? p1 + d1 : p1;
            p2 = vld ? p2 + d2 : p2;
            #pragma unroll
            for (int k2 = 0; k2 < 9; k2++) R[k2] = vld ? Nw[k2] : R[k2];
        }

        float* so = s_out + t * OUTW;
        so[0] = p0; so[1] = p1; so[2] = p2;
        so[3] = p0 + ob[0]; so[4] = p1 + ob[1]; so[5] = p2 + ob[2];  // gpos = pos + root xyz
        #pragma unroll
        for (int k = 0; k < 9; k++) so[6+k] = R[k];
    }
    __syncthreads();

    // ---- flush: destination runs are fully contiguous per block ----
    {
        float* dp = out_pos  + (size_t)g0 * 75;
        float* dg = out_gpos + (size_t)g0 * 75;
        for (int idx = t; idx < ng * 75; idx += THREADS) {
            const int row = idx / 3;
            const int k   = idx - row * 3;
            dp[idx] = s_out[row * OUTW + k];
            dg[idx] = s_out[row * OUTW + 3 + k];
        }
        float* dr = out_rot + (size_t)g0 * 225;
        for (int idx = t; idx < ng * 225; idx += THREADS) {
            const int row = idx / 9;
            const int k   = idx - row * 9;
            dr[idx] = s_out[row * OUTW + 6 + k];
        }
    }
}

extern "C" void kernel_launch(void* const* d_in, const int* in_sizes, int n_in,
                              void* d_out, int out_size)
{
    const float* x = (const float*)d_in[0];
    const int gn = in_sizes[0];          // G * 25
    const int G  = gn / NN;

    const float* off = nullptr;
    const float* axis = nullptr;
    for (int i = 1; i < n_in; i++) {
        if (in_sizes[i] == 6 * gn) off = (const float*)d_in[i];
        else if (in_sizes[i] == 3 * gn && axis == nullptr) axis = (const float*)d_in[i];
    }

    float* out = (float*)d_out;
    float* out_pos  = out;                    // G*N*3
    float* out_rot  = out + (size_t)gn * 3;   // G*N*9
    float* out_gpos = out + (size_t)gn * 12;  // G*N*3
    (void)out_size;

    const int blocks = (G + GPBK - 1) / GPBK;
    fk_kernel<<<blocks, THREADS>>>(x, off, axis, out_pos, out_rot, out_gpos, G);
}

// round 9
// speedup vs baseline: 3.9683x; 1.1863x over previous
#include <cuda_runtime.h>

#define NN     25
#define GPBK   8               // graphs per block
#define THREADS 224            // 200 compute threads (8*25)
#define LW     12              // s_L row: L[9] + xyz[3]; 48B, 16B-aligned
#define ROWS_G 26              // 25 nodes + identity row

// packed root-paths (4 bytes: a0|a1<<8|a2<<16|a3<<24), pad = 25 (identity row)
#define PD 25
__constant__ unsigned int c_pp[NN] = {
    (PD)|(PD<<8)|(PD<<16)|(PD<<24),                       // 0
    (1u)|(PD<<8)|(PD<<16)|(PD<<24),                       // 1
    (2u)|(PD<<8)|(PD<<16)|(PD<<24),                       // 2
    (1u)|(3u<<8)|(PD<<16)|(PD<<24),                       // 3
    (1u)|(4u<<8)|(PD<<16)|(PD<<24),                       // 4
    (2u)|(5u<<8)|(PD<<16)|(PD<<24),                       // 5
    (2u)|(6u<<8)|(PD<<16)|(PD<<24),                       // 6
    (1u)|(3u<<8)|(7u<<16)|(PD<<24),                       // 7
    (1u)|(3u<<8)|(8u<<16)|(PD<<24),                       // 8
    (1u)|(4u<<8)|(9u<<16)|(PD<<24),                       // 9
    (1u)|(4u<<8)|(10u<<16)|(PD<<24),                      // 10
    (2u)|(5u<<8)|(11u<<16)|(PD<<24),                      // 11
    (2u)|(5u<<8)|(12u<<16)|(PD<<24),                      // 12
    (2u)|(6u<<8)|(13u<<16)|(PD<<24),                      // 13
    (2u)|(6u<<8)|(14u<<16)|(PD<<24),                      // 14
    (1u)|(3u<<8)|(7u<<16)|(15u<<24),                      // 15
    (1u)|(3u<<8)|(7u<<16)|(16u<<24),                      // 16
    (1u)|(3u<<8)|(8u<<16)|(17u<<24),                      // 17
    (1u)|(3u<<8)|(8u<<16)|(18u<<24),                      // 18
    (1u)|(4u<<8)|(9u<<16)|(19u<<24),                      // 19
    (1u)|(4u<<8)|(9u<<16)|(20u<<24),                      // 20
    (1u)|(4u<<8)|(10u<<16)|(21u<<24),                     // 21
    (1u)|(4u<<8)|(10u<<16)|(22u<<24),                     // 22
    (2u)|(5u<<8)|(11u<<16)|(23u<<24),                     // 23
    (2u)|(5u<<8)|(11u<<16)|(24u<<24)                      // 24
};

__global__ void __launch_bounds__(THREADS, 7)
fk_kernel(const float* __restrict__ x,
          const float* __restrict__ off,
          const float* __restrict__ axis,
          float* __restrict__ out_pos,
          float* __restrict__ out_rot,
          float* __restrict__ out_gpos,
          int G)
{
    __shared__ __align__(16) float s_off[GPBK * NN * 6];          // 1200 (natural layout)
    __shared__ __align__(16) float s_L  [GPBK * ROWS_G * LW];     // 2496
    __shared__ __align__(16) float s_pos[GPBK * NN * 3];          // 600 (output layout)
    __shared__ __align__(16) float s_gps[GPBK * NN * 3];          // 600
    __shared__ __align__(16) float s_rot[GPBK * NN * 9];          // 1800
    __shared__ float4 s_ax[NN];
    __shared__ unsigned int s_pp[NN];

    const int t  = threadIdx.x;
    const int g0 = blockIdx.x * GPBK;
    const int ng = min(GPBK, G - g0);
    const int NT = ng * NN;

    // ---- stage: axis, paths, offsets, identity rows ----
    if (t < NN) {
        const float a0 = axis[t*3+0], a1 = axis[t*3+1], a2 = axis[t*3+2];
        s_ax[t] = make_float4(a0, a1, a2, sqrtf(a0*a0 + a1*a1 + a2*a2));
        s_pp[t] = c_pp[t];
    }
    if (ng == GPBK) {
        const float4* srcv = (const float4*)(off + (size_t)g0 * 150);
        float4* dv = (float4*)s_off;
        #pragma unroll 2
        for (int i = t; i < GPBK * 150 / 4; i += THREADS) dv[i] = srcv[i];
    } else {
        const float* src = off + (size_t)g0 * 150;
        for (int i = t; i < NT * 6; i += THREADS) s_off[i] = src[i];
    }
    // identity rows (row 25 of each graph): L = I, xyz = 0
    if (t < GPBK * LW) {
        const int gl = t / LW, j = t - gl * LW;
        s_L[(gl * ROWS_G + PD) * LW + j] = (j == 0 || j == 4 || j == 8) ? 1.f : 0.f;
    }
    __syncthreads();

    // ---- phase 1: per-node local matrix -> fused row [L0..8, ox,oy,oz] ----
    if (t < NT) {
        const int gl = t / NN;
        const int i  = t - gl * NN;
        const float* o = s_off + t * 6;
        const float4 ax = s_ax[i];
        const float th = x[(size_t)g0 * NN + t] * ax.w;     // coalesced LDG
        const float ox = o[0], oy = o[1], oz = o[2];

        float sx,cx,sy,cy,sz,cz,st,ct;
        __sincosf(o[3], &sx, &cx);
        __sincosf(o[4], &sy, &cy);
        __sincosf(o[5], &sz, &cz);
        __sincosf(th,  &st, &ct);

        const float e00=cz*cy,            e10=sz*cy,            e20=-sy;
        const float e01=cz*sy*sx - sz*cx, e11=sz*sy*sx + cz*cx, e21=cy*sx;
        const float e02=cz*sy*cx + sz*sx, e12=sz*sy*cx - cz*sx, e22=cy*cx;

        const float v=1.f-ct, n1=ax.x, n2=ax.y, n3=ax.z;
        const float n12v=n1*n2*v, n13v=n1*n3*v, n23v=n2*n3*v;
        const float r00=ct+n1*n1*v, r01=n12v-n3*st, r02=n13v+n2*st;
        const float r10=n12v+n3*st, r11=ct+n2*n2*v, r12=n23v-n1*st;
        const float r20=n13v-n2*st, r21=n23v+n1*st, r22=ct+n3*n3*v;

        float4 A, B, C;
        A.x=e00*r00+e01*r10+e02*r20; A.y=e00*r01+e01*r11+e02*r21; A.z=e00*r02+e01*r12+e02*r22;
        A.w=e10*r00+e11*r10+e12*r20; B.x=e10*r01+e11*r11+e12*r21; B.y=e10*r02+e11*r12+e12*r22;
        B.z=e20*r00+e21*r10+e22*r20; B.w=e20*r01+e21*r11+e22*r21; C.x=e20*r02+e21*r12+e22*r22;
        C.y=ox; C.z=oy; C.w=oz;

        float4* row = (float4*)(s_L + (gl * ROWS_G + i) * LW);
        row[0] = A; row[1] = B; row[2] = C;
    }
    __syncthreads();

    // ---- phase 2: prefix-product walk via LDS.128 rows, identity padding ----
    if (t < NT) {
        const int gl = t / NN;
        const int i  = t - gl * NN;
        const float* Lg = s_L + gl * ROWS_G * LW;
        unsigned int pk = s_pp[i];

        // root row
        const float4* rp = (const float4*)Lg;
        float4 A = rp[0], B = rp[1], C = rp[2];
        float R0=A.x,R1=A.y,R2=A.z,R3=A.w,R4=B.x,R5=B.y,R6=B.z,R7=B.w,R8=C.x;
        const float rx=C.y, ry=C.z, rz=C.w;
        float p0=0.f, p1=0.f, p2=0.f;

        #pragma unroll
        for (int k = 0; k < 4; k++) {
            const int a = pk & 255u; pk >>= 8;
            const float4* ap = (const float4*)(Lg + a * LW);
            const float4 LA = ap[0], LB = ap[1], LC = ap[2];
            // d = R * xyz_a ; p += d
            p0 += R0*LC.y + R1*LC.z + R2*LC.w;
            p1 += R3*LC.y + R4*LC.z + R5*LC.w;
            p2 += R6*LC.y + R7*LC.z + R8*LC.w;
            // R = R * L_a
            const float n0 = R0*LA.x + R1*LA.w + R2*LB.z;
            const float n1_ = R0*LA.y + R1*LB.x + R2*LB.w;
            const float n2_ = R0*LA.z + R1*LB.y + R2*LC.x;
            const float n3_ = R3*LA.x + R4*LA.w + R5*LB.z;
            const float n4 = R3*LA.y + R4*LB.x + R5*LB.w;
            const float n5 = R3*LA.z + R4*LB.y + R5*LC.x;
            const float n6 = R6*LA.x + R7*LA.w + R8*LB.z;
            const float n7 = R6*LA.y + R7*LB.x + R8*LB.w;
            const float n8 = R6*LA.z + R7*LB.y + R8*LC.x;
            R0=n0; R1=n1_; R2=n2_; R3=n3_; R4=n4; R5=n5; R6=n6; R7=n7; R8=n8;
        }

        // stage outputs in final layout
        float* sp = s_pos + t * 3;
        float* sg = s_gps + t * 3;
        float* sr = s_rot + t * 9;
        sp[0]=p0; sp[1]=p1; sp[2]=p2;
        sg[0]=p0+rx; sg[1]=p1+ry; sg[2]=p2+rz;
        sr[0]=R0; sr[1]=R1; sr[2]=R2; sr[3]=R3; sr[4]=R4;
        sr[5]=R5; sr[6]=R6; sr[7]=R7; sr[8]=R8;
    }
    __syncthreads();

    // ---- flush: pure copies (layouts match), vectorized when block is full ----
    if (ng == GPBK) {
        const float4* sp4 = (const float4*)s_pos;
        const float4* sg4 = (const float4*)s_gps;
        const float4* sr4 = (const float4*)s_rot;
        float4* dp4 = (float4*)(out_pos  + (size_t)g0 * 75);
        float4* dg4 = (float4*)(out_gpos + (size_t)g0 * 75);
        float4* dr4 = (float4*)(out_rot  + (size_t)g0 * 225);
        #pragma unroll 4
        for (int idx = t; idx < 750; idx += THREADS) {
            if (idx < 150)      dp4[idx]       = sp4[idx];
            else if (idx < 300) dg4[idx - 150] = sg4[idx - 150];
            else                dr4[idx - 300] = sr4[idx - 300];
        }
    } else {
        float* dp = out_pos  + (size_t)g0 * 75;
        float* dg = out_gpos + (size_t)g0 * 75;
        float* dr = out_rot  + (size_t)g0 * 225;
        for (int idx = t; idx < NT * 3; idx += THREADS) { dp[idx] = s_pos[idx]; dg[idx] = s_gps[idx]; }
        for (int idx = t; idx < NT * 9; idx += THREADS) dr[idx] = s_rot[idx];
    }
}

extern "C" void kernel_launch(void* const* d_in, const int* in_sizes, int n_in,
                              void* d_out, int out_size)
{
    const float* x = (const float*)d_in[0];
    const int gn = in_sizes[0];          // G * 25
    const int G  = gn / NN;

    const float* off = nullptr;
    const float* axis = nullptr;
    for (int i = 1; i < n_in; i++) {
        if (in_sizes[i] == 6 * gn) off = (const float*)d_in[i];
        else if (in_sizes[i] == 3 * gn && axis == nullptr) axis = (const float*)d_in[i];
    }

    float* out = (float*)d_out;
    float* out_pos  = out;                    // G*N*3
    float* out_rot  = out + (size_t)gn * 3;   // G*N*9
    float* out_gpos = out + (size_t)gn * 12;  // G*N*3
    (void)out_size;

    const int blocks = (G + GPBK - 1) / GPBK;
    fk_kernel<<<blocks, THREADS>>>(x, off, axis, out_pos, out_rot, out_gpos, G);
}

// round 10
// speedup vs baseline: 3.9939x; 1.0064x over previous
#include <cuda_runtime.h>

#define NN     25
#define GPBK   16              // graphs per block
#define THREADS 448            // 400 compute threads (16*25), warp-aligned depth classes
#define LW     12              // s_L row: L[9] + xyz[3]; 48B, 16B-aligned

// packed root-paths, low byte = root child ... high = self (unused bytes = 0)
__constant__ unsigned int c_pp[NN] = {
    0u,                                   // 0 (root, unused)
    1u,                                   // 1
    2u,                                   // 2
    (1u)|(3u<<8),                         // 3
    (1u)|(4u<<8),                         // 4
    (2u)|(5u<<8),                         // 5
    (2u)|(6u<<8),                         // 6
    (1u)|(3u<<8)|(7u<<16),                // 7
    (1u)|(3u<<8)|(8u<<16),                // 8
    (1u)|(4u<<8)|(9u<<16),                // 9
    (1u)|(4u<<8)|(10u<<16),               // 10
    (2u)|(5u<<8)|(11u<<16),               // 11
    (2u)|(5u<<8)|(12u<<16),               // 12
    (2u)|(6u<<8)|(13u<<16),               // 13
    (2u)|(6u<<8)|(14u<<16),               // 14
    (1u)|(3u<<8)|(7u<<16)|(15u<<24),      // 15
    (1u)|(3u<<8)|(7u<<16)|(16u<<24),      // 16
    (1u)|(3u<<8)|(8u<<16)|(17u<<24),      // 17
    (1u)|(3u<<8)|(8u<<16)|(18u<<24),      // 18
    (1u)|(4u<<8)|(9u<<16)|(19u<<24),      // 19
    (1u)|(4u<<8)|(9u<<16)|(20u<<24),      // 20
    (1u)|(4u<<8)|(10u<<16)|(21u<<24),     // 21
    (1u)|(4u<<8)|(10u<<16)|(22u<<24),     // 22
    (2u)|(5u<<8)|(11u<<16)|(23u<<24),     // 23
    (2u)|(5u<<8)|(11u<<16)|(24u<<24)      // 24
};

// exact-depth prefix-product walk; reads fused rows [L0..8 | ox,oy,oz] via LDS.128
template<int STEPS>
__device__ __forceinline__ void walk_store(
    const float* __restrict__ Lg, unsigned int pk,
    float* __restrict__ sp, float* __restrict__ sg, float* __restrict__ sr)
{
    const float4* rp = (const float4*)Lg;          // root row
    const float4 A = rp[0], B = rp[1], C = rp[2];
    float R0=A.x,R1=A.y,R2=A.z,R3=A.w,R4=B.x,R5=B.y,R6=B.z,R7=B.w,R8=C.x;
    const float rx=C.y, ry=C.z, rz=C.w;
    float p0=0.f, p1=0.f, p2=0.f;

    #pragma unroll
    for (int k = 0; k < STEPS; k++) {
        const int a = pk & 255u; pk >>= 8;
        const float4* ap = (const float4*)(Lg + a * LW);
        const float4 LA = ap[0], LB = ap[1], LC = ap[2];
        p0 += R0*LC.y + R1*LC.z + R2*LC.w;
        p1 += R3*LC.y + R4*LC.z + R5*LC.w;
        p2 += R6*LC.y + R7*LC.z + R8*LC.w;
        const float n0 = R0*LA.x + R1*LA.w + R2*LB.z;
        const float n1 = R0*LA.y + R1*LB.x + R2*LB.w;
        const float n2 = R0*LA.z + R1*LB.y + R2*LC.x;
        const float n3 = R3*LA.x + R4*LA.w + R5*LB.z;
        const float n4 = R3*LA.y + R4*LB.x + R5*LB.w;
        const float n5 = R3*LA.z + R4*LB.y + R5*LC.x;
        const float n6 = R6*LA.x + R7*LA.w + R8*LB.z;
        const float n7 = R6*LA.y + R7*LB.x + R8*LB.w;
        const float n8 = R6*LA.z + R7*LB.y + R8*LC.x;
        R0=n0; R1=n1; R2=n2; R3=n3; R4=n4; R5=n5; R6=n6; R7=n7; R8=n8;
    }

    sp[0]=p0; sp[1]=p1; sp[2]=p2;
    sg[0]=p0+rx; sg[1]=p1+ry; sg[2]=p2+rz;
    sr[0]=R0; sr[1]=R1; sr[2]=R2; sr[3]=R3; sr[4]=R4;
    sr[5]=R5; sr[6]=R6; sr[7]=R7; sr[8]=R8;
}

__global__ void __launch_bounds__(THREADS, 3)
fk_kernel(const float* __restrict__ x,
          const float* __restrict__ off,
          const float* __restrict__ axis,
          float* __restrict__ out_pos,
          float* __restrict__ out_rot,
          float* __restrict__ out_gpos,
          int G)
{
    __shared__ __align__(16) float s_off[GPBK * NN * 6];   // 2400
    __shared__ __align__(16) float s_L  [GPBK * NN * LW];  // 4800
    __shared__ __align__(16) float s_pos[GPBK * NN * 3];   // 1200 (output layout)
    __shared__ __align__(16) float s_gps[GPBK * NN * 3];   // 1200
    __shared__ __align__(16) float s_rot[GPBK * NN * 9];   // 3600
    __shared__ float4 s_ax[NN];
    __shared__ unsigned int s_pp[NN];

    const int t  = threadIdx.x;
    const int g0 = blockIdx.x * GPBK;
    const int ng = min(GPBK, G - g0);
    const int NT = ng * NN;

    // ---- stage axis/paths/offsets ----
    if (t < NN) {
        const float a0 = axis[t*3+0], a1 = axis[t*3+1], a2 = axis[t*3+2];
        s_ax[t] = make_float4(a0, a1, a2, sqrtf(a0*a0 + a1*a1 + a2*a2));
        s_pp[t] = c_pp[t];
    }
    if (ng == GPBK) {
        const float4* srcv = (const float4*)(off + (size_t)g0 * 150);
        float4* dv = (float4*)s_off;
        #pragma unroll 2
        for (int i = t; i < GPBK * 150 / 4; i += THREADS) dv[i] = srcv[i];
    } else {
        const float* src = off + (size_t)g0 * 150;
        for (int i = t; i < NT * 6; i += THREADS) s_off[i] = src[i];
    }
    __syncthreads();

    // ---- phase 1: per-node local matrix -> fused row [L0..8, ox,oy,oz] ----
    if (t < NT) {
        const int i = t - 25 * (t / 25);
        const float* o = s_off + t * 6;
        const float4 ax = s_ax[i];
        const float th = x[(size_t)g0 * NN + t] * ax.w;     // coalesced LDG
        const float ox = o[0], oy = o[1], oz = o[2];

        float sx,cx,sy,cy,sz,cz,st,ct;
        __sincosf(o[3], &sx, &cx);
        __sincosf(o[4], &sy, &cy);
        __sincosf(o[5], &sz, &cz);
        __sincosf(th,  &st, &ct);

        const float e00=cz*cy,            e10=sz*cy,            e20=-sy;
        const float e01=cz*sy*sx - sz*cx, e11=sz*sy*sx + cz*cx, e21=cy*sx;
        const float e02=cz*sy*cx + sz*sx, e12=sz*sy*cx - cz*sx, e22=cy*cx;

        const float v=1.f-ct, n1=ax.x, n2=ax.y, n3=ax.z;
        const float n12v=n1*n2*v, n13v=n1*n3*v, n23v=n2*n3*v;
        const float r00=ct+n1*n1*v, r01=n12v-n3*st, r02=n13v+n2*st;
        const float r10=n12v+n3*st, r11=ct+n2*n2*v, r12=n23v-n1*st;
        const float r20=n13v-n2*st, r21=n23v+n1*st, r22=ct+n3*n3*v;

        float4 A, B, C;
        A.x=e00*r00+e01*r10+e02*r20; A.y=e00*r01+e01*r11+e02*r21; A.z=e00*r02+e01*r12+e02*r22;
        A.w=e10*r00+e11*r10+e12*r20; B.x=e10*r01+e11*r11+e12*r21; B.y=e10*r02+e11*r12+e12*r22;
        B.z=e20*r00+e21*r10+e22*r20; B.w=e20*r01+e21*r11+e22*r21; C.x=e20*r02+e21*r12+e22*r22;
        C.y=ox; C.z=oy; C.w=oz;

        float4* row = (float4*)(s_L + t * LW);
        row[0] = A; row[1] = B; row[2] = C;
    }
    __syncthreads();

    // ---- phase 2: depth-classed walk; classes are whole warps, loops exactly unrolled ----
    // [0,160): depth-4 leaves 15..24   (5 warps)
    // [160,288): depth-3 nodes 7..14   (4 warps)
    // [288,352): depth-2 nodes 3..6    (2 warps)
    // [352,384): depth-1 nodes 1..2    (1 warp)
    // [384,400): root node 0           (half warp)
    if (t < 160) {
        const int g = t / 10, node = 15 + (t - g * 10);
        if (g < ng) {
            const int r = g * NN + node;
            walk_store<4>(s_L + g*NN*LW, s_pp[node], s_pos + r*3, s_gps + r*3, s_rot + r*9);
        }
    } else if (t < 288) {
        const int i = t - 160, g = i >> 3, node = 7 + (i & 7);
        if (g < ng) {
            const int r = g * NN + node;
            walk_store<3>(s_L + g*NN*LW, s_pp[node], s_pos + r*3, s_gps + r*3, s_rot + r*9);
        }
    } else if (t < 352) {
        const int i = t - 288, g = i >> 2, node = 3 + (i & 3);
        if (g < ng) {
            const int r = g * NN + node;
            walk_store<2>(s_L + g*NN*LW, s_pp[node], s_pos + r*3, s_gps + r*3, s_rot + r*9);
        }
    } else if (t < 384) {
        const int i = t - 352, g = i >> 1, node = 1 + (i & 1);
        if (g < ng) {
            const int r = g * NN + node;
            walk_store<1>(s_L + g*NN*LW, s_pp[node], s_pos + r*3, s_gps + r*3, s_rot + r*9);
        }
    } else if (t < 400) {
        const int g = t - 384;
        if (g < ng) {
            const int r = g * NN;
            walk_store<0>(s_L + g*NN*LW, 0u, s_pos + r*3, s_gps + r*3, s_rot + r*9);
        }
    }
    __syncthreads();

    // ---- flush: pure copies (layouts match), vectorized when block is full ----
    if (ng == GPBK) {
        const float4* sp4 = (const float4*)s_pos;
        const float4* sg4 = (const float4*)s_gps;
        const float4* sr4 = (const float4*)s_rot;
        float4* dp4 = (float4*)(out_pos  + (size_t)g0 * 75);
        float4* dg4 = (float4*)(out_gpos + (size_t)g0 * 75);
        float4* dr4 = (float4*)(out_rot  + (size_t)g0 * 225);
        #pragma unroll 4
        for (int idx = t; idx < 1500; idx += THREADS) {
            if (idx < 300)      dp4[idx]       = sp4[idx];
            else if (idx < 600) dg4[idx - 300] = sg4[idx - 300];
            else                dr4[idx - 600] = sr4[idx - 600];
        }
    } else {
        float* dp = out_pos  + (size_t)g0 * 75;
        float* dg = out_gpos + (size_t)g0 * 75;
        float* dr = out_rot  + (size_t)g0 * 225;
        for (int idx = t; idx < NT * 3; idx += THREADS) { dp[idx] = s_pos[idx]; dg[idx] = s_gps[idx]; }
        for (int idx = t; idx < NT * 9; idx += THREADS) dr[idx] = s_rot[idx];
    }
}

extern "C" void kernel_launch(void* const* d_in, const int* in_sizes, int n_in,
                              void* d_out, int out_size)
{
    const float* x = (const float*)d_in[0];
    const int gn = in_sizes[0];          // G * 25
    const int G  = gn / NN;

    const float* off = nullptr;
    const float* axis = nullptr;
    for (int i = 1; i < n_in; i++) {
        if (in_sizes[i] == 6 * gn) off = (const float*)d_in[i];
        else if (in_sizes[i] == 3 * gn && axis == nullptr) axis = (const float*)d_in[i];
    }

    float* out = (float*)d_out;
    float* out_pos  = out;                    // G*N*3
    float* out_rot  = out + (size_t)gn * 3;   // G*N*9
    float* out_gpos = out + (size_t)gn * 12;  // G*N*3
    (void)out_size;

    const int blocks = (G + GPBK - 1) / GPBK;
    fk_kernel<<<blocks, THREADS>>>(x, off, axis, out_pos, out_rot, out_gpos, G);
}